// round 8
// baseline (speedup 1.0000x reference)
#include <cuda_runtime.h>
#include <cstdint>

#define T    200
#define D    64
#define H1D  80
#define H2D  40
#define TP   202   // even stride: 8B-aligned (t,t+1) pairs for LDS.64/STS.64

#define NEG_BIG (-2147483648.0f)

// Shared memory layout (floats):
//  f_t  [64][202], h1t [80][202], h2t [40][202]
//  WbP  [64][80] duplicated pairs {w,w}  (8B each)
//  W2P  [80][40] duplicated pairs {w,w}
//  qs[64] bb[80] b2s[40] W3s[40] wts[200] red[680]
#define SM_FLOATS (64*TP + 80*TP + 40*TP + 64*80*2 + 80*40*2 + 64 + 80 + 40 + 40 + 200 + 680)
#define SM_BYTES  (SM_FLOATS * 4)

__device__ __forceinline__ float fsigmoid(float x) {
    return __fdividef(1.0f, 1.0f + __expf(-x));
}

// ---- packed f32x2 helpers ----
__device__ __forceinline__ void upk2(unsigned long long v, float& lo, float& hi) {
    unsigned int a, b;
    asm("mov.b64 {%0, %1}, %2;" : "=r"(a), "=r"(b) : "l"(v));
    lo = __uint_as_float(a);
    hi = __uint_as_float(b);
}
__device__ __forceinline__ void fma2(unsigned long long& d,
                                     unsigned long long a, unsigned long long b) {
    asm("fma.rn.f32x2 %0, %1, %2, %3;" : "=l"(d) : "l"(a), "l"(b), "l"(d));
}

__global__ __launch_bounds__(1024, 1)
void attn_layer_kernel(const float* __restrict__ query,
                       const float* __restrict__ fact,
                       const int*   __restrict__ mask,
                       const float* __restrict__ W1,
                       const float* __restrict__ b1,
                       const float* __restrict__ W2,
                       const float* __restrict__ b2,
                       const float* __restrict__ W3,
                       const float* __restrict__ b3,
                       float* __restrict__ out)
{
    extern __shared__ float sm[];
    float* f_t = sm;                    // [64][TP]
    float* h1t = f_t + 64 * TP;         // [80][TP]
    float* h2t = h1t + 80 * TP;         // [40][TP]
    float* WbP = h2t + 40 * TP;         // [64][80] pairs (16B aligned)
    float* W2P = WbP + 64 * 80 * 2;     // [80][40] pairs (16B aligned)
    float* qs  = W2P + 80 * 40 * 2;     // [64]
    float* bb  = qs  + 64;              // [80]
    float* b2s = bb  + 80;              // [40]
    float* W3s = b2s + 40;              // [40]
    float* wts = W3s + 40;              // [200]
    float* red = wts + 200;             // [680]

    const int b    = blockIdx.x;
    const int tid  = threadIdx.x;
    const int lane = tid & 31;
    const int wid  = tid >> 5;

    // ---- prefetch long-latency scalars ----
    int my_mask = 0;
    if (tid < T) my_mask = mask[(size_t)b * T + tid];
    const float b3v = b3[0];

    // ---- Stage 0: q + small constants + duplicated W2 pairs ----
    if (tid < D) qs[tid] = query[b * D + tid];
    if (tid >= 64 && tid < 64 + H2D) {
        int k = tid - 64;
        b2s[k] = b2[k];
        W3s[k] = W3[k];
    }
    for (int i = tid; i < H1D * H2D; i += 1024) {
        float w = W2[i];
        ((float2*)W2P)[i] = make_float2(w, w);
    }
    __syncthreads();   // qs ready

    // ---- Stage 1: fact transpose (LDG.128) + folded W1 (duplicated pairs) ----
    const float4* fb4 = (const float4*)(fact + (size_t)b * T * D);
    for (int v = tid; v < T * D / 4; v += 1024) {
        float4 x = fb4[v];
        int t  = v >> 4;
        int d0 = (v & 15) * 4;
        f_t[(d0 + 0) * TP + t] = x.x;
        f_t[(d0 + 1) * TP + t] = x.y;
        f_t[(d0 + 2) * TP + t] = x.z;
        f_t[(d0 + 3) * TP + t] = x.w;
    }
    // WbP[d][h] = {(W1a-W1d) + q[d]*W1c, same}
    for (int e = tid; e < D * H1D; e += 1024) {
        int d = e / H1D, h = e - d * H1D;
        float a  = W1[d * H1D + h];
        float cc = W1[(128 + d) * H1D + h];
        float dd = W1[(192 + d) * H1D + h];
        float wb = (a - dd) + qs[d] * cc;
        ((float2*)WbP)[e] = make_float2(wb, wb);
    }
    // bias partials: bb[h] = b1[h] + sum_d q[d]*(W1b+W1d)[d][h]
    if (tid < 640) {
        const int h = tid % 80;
        const int c = tid / 80;            // 8 chunks of 8 d
        float s = 0.0f;
        #pragma unroll 4
        for (int d = c * 8; d < c * 8 + 8; d++)
            s += qs[d] * (W1[(64 + d) * H1D + h] + W1[(192 + d) * H1D + h]);
        red[c * 80 + h] = s;
    }
    __syncthreads();
    if (tid < H1D) {
        float s = b1[tid];
        #pragma unroll
        for (int c = 0; c < 8; c++) s += red[c * 80 + tid];
        bb[tid] = s;
    }
    __syncthreads();

    // ---- Stage 2: GEMM1  h1[t][h] = sigmoid(f[t,:] @ Wb[:,h] + bb[h]) ----
    // 1000 threads: hg = tid/100 (h block of 8), pg = tid%100, t-pair {2pg, 2pg+1}.
    // Activation: natural pair via LDS.64. Weights: pre-duplicated, LDS.128 -> 2 operands.
    if (tid < 1000) {
        const int hg = tid / 100;
        const int pg = tid % 100;
        unsigned long long acc[8];
        #pragma unroll
        for (int j = 0; j < 8; j++) acc[j] = 0ULL;

        #pragma unroll 4
        for (int d = 0; d < D; d++) {
            unsigned long long f2 =
                *(const unsigned long long*)(f_t + d * TP + 2 * pg);
            const ulonglong2* wv = (const ulonglong2*)(WbP + d * 160 + hg * 16);
            ulonglong2 wA = wv[0];   // {h0,h0},{h1,h1}
            ulonglong2 wB = wv[1];   // {h2,h2},{h3,h3}
            ulonglong2 wC = wv[2];   // {h4,h4},{h5,h5}
            ulonglong2 wD = wv[3];   // {h6,h6},{h7,h7}
            fma2(acc[0], f2, wA.x);
            fma2(acc[1], f2, wA.y);
            fma2(acc[2], f2, wB.x);
            fma2(acc[3], f2, wB.y);
            fma2(acc[4], f2, wC.x);
            fma2(acc[5], f2, wC.y);
            fma2(acc[6], f2, wD.x);
            fma2(acc[7], f2, wD.y);
        }
        #pragma unroll
        for (int j = 0; j < 8; j++) {
            const int h = hg * 8 + j;
            const float bias = bb[h];
            float a0, a1;
            upk2(acc[j], a0, a1);
            float2 r = make_float2(fsigmoid(a0 + bias), fsigmoid(a1 + bias));
            *(float2*)(h1t + h * TP + 2 * pg) = r;
        }
    }
    __syncthreads();

    // ---- Stage 3: GEMM2  h2[t][k] = sigmoid(h1[t,:] @ W2[:,k] + b2[k]) ----
    // 1000 threads: kg = tid/100 (k block of 4), pg = tid%100, t-pair {2pg, 2pg+1}.
    if (tid < 1000) {
        const int kg = tid / 100;
        const int pg = tid % 100;
        unsigned long long acc[4];
        #pragma unroll
        for (int j = 0; j < 4; j++) acc[j] = 0ULL;

        #pragma unroll 4
        for (int h = 0; h < H1D; h++) {
            unsigned long long a2 =
                *(const unsigned long long*)(h1t + h * TP + 2 * pg);
            const ulonglong2* wv = (const ulonglong2*)(W2P + h * 80 + kg * 8);
            ulonglong2 w01 = wv[0];   // {k0,k0},{k1,k1}
            ulonglong2 w23 = wv[1];   // {k2,k2},{k3,k3}
            fma2(acc[0], a2, w01.x);
            fma2(acc[1], a2, w01.y);
            fma2(acc[2], a2, w23.x);
            fma2(acc[3], a2, w23.y);
        }
        #pragma unroll
        for (int j = 0; j < 4; j++) {
            const int k = kg * 4 + j;
            const float bias = b2s[k];
            float a0, a1;
            upk2(acc[j], a0, a1);
            float2 r = make_float2(fsigmoid(a0 + bias), fsigmoid(a1 + bias));
            *(float2*)(h2t + k * TP + 2 * pg) = r;
        }
    }
    __syncthreads();

    // ---- Stage 4: scores + masked softmax (no-max: scores bounded, exp safe) ----
    float e = 0.0f;
    if (tid < T) {
        float s = b3v;
        #pragma unroll 8
        for (int k = 0; k < H2D; k++)
            s = fmaf(h2t[k * TP + tid], W3s[k], s);
        if (my_mask == 1) e = __expf(s);   // masked lanes stay 0
    }
    float s2 = e;
    #pragma unroll
    for (int o = 16; o; o >>= 1) s2 += __shfl_xor_sync(0xffffffffu, s2, o);
    if (lane == 0) red[wid] = s2;
    __syncthreads();
    if (wid == 0) {
        float v = red[lane];
        #pragma unroll
        for (int o = 16; o; o >>= 1) v += __shfl_xor_sync(0xffffffffu, v, o);
        if (lane == 0) red[512] = v;
    }
    __syncthreads();
    const float inv_sum = __fdividef(1.0f, fmaxf(red[512], 1e-30f));
    if (tid < T) wts[tid] = e * inv_sum;
    __syncthreads();

    // ---- Stage 5: out[b][d] = sum_t wts[t] * fact[t][d] ----
    if (tid < 512) {
        const int d = tid & 63;
        const int c = tid >> 6;        // 8 chunks of 25 t
        float s = 0.0f;
        const int t0 = c * 25;
        #pragma unroll 5
        for (int t = t0; t < t0 + 25; t++)
            s = fmaf(wts[t], f_t[d * TP + t], s);
        red[c * 64 + d] = s;
    }
    __syncthreads();
    if (tid < D) {
        float s = 0.0f;
        #pragma unroll
        for (int c = 0; c < 8; c++) s += red[c * 64 + tid];
        out[(size_t)b * D + tid] = s;
    }
}

extern "C" void kernel_launch(void* const* d_in, const int* in_sizes, int n_in,
                              void* d_out, int out_size)
{
    const float* query = (const float*)d_in[0];
    const float* fact  = (const float*)d_in[1];
    const int*   mask  = (const int*)  d_in[2];
    const float* W1    = (const float*)d_in[3];
    const float* b1    = (const float*)d_in[4];
    const float* W2    = (const float*)d_in[5];
    const float* b2    = (const float*)d_in[6];
    const float* W3    = (const float*)d_in[7];
    const float* b3    = (const float*)d_in[8];
    float* out = (float*)d_out;

    const int nb = in_sizes[0] / D;

    cudaFuncSetAttribute(attn_layer_kernel,
                         cudaFuncAttributeMaxDynamicSharedMemorySize, SM_BYTES);
    attn_layer_kernel<<<nb, 1024, SM_BYTES>>>(query, fact, mask, W1, b1, W2, b2, W3, b3, out);
}